// round 14
// baseline (speedup 1.0000x reference)
#include <cuda_runtime.h>
#include <math.h>
#include <stdint.h>

#define N_NODES 100000
#define N_EDGES 1000000
#define D_NODE 64
#define D_EDGE 16
#define NUM_PAR 80
#define HIDDEN 160

#define NBLOCKS 592               // 148 SMs x 4 blocks, all co-resident
#define NTHREADS 256              // 8 warps
#define EPT 7                     // edges per thread == tiles per block
#define TILE_E 256                // edges per tile (1 per thread)
#define TILE_B (TILE_E * 64)      // 16384 bytes
#define NBUF 2
#define SMEM_DYN (NBUF * TILE_B)  // 32768B dynamic + 328B static < 48KB: no opt-in needed

// Scratch (allocation-free rule).
__device__ float g_p[N_NODES];
__device__ int   g_cnt;           // barrier arrivals (self-resetting)
__device__ volatile int g_flag;   // barrier generation (monotone across replays)

#define CP_WAIT(n) asm volatile("cp.async.wait_group %0;" :: "n"(n))

// Issue one 16KB tile: thread t copies quads {i*256+t}, gmem-coalesced
// (512B per warp-instruction), into XOR-swizzled smem chunks.
__device__ __forceinline__ void issue_tile(uint32_t sbuf, const char* __restrict__ ea,
                                           int tile_start, int t) {
    #pragma unroll
    for (int i = 0; i < 4; i++) {
        int Q = i * 256 + t;                       // quad index within tile
        int row = Q >> 2, jq = Q & 3;
        int chunk = (row << 2) + (jq ^ ((row >> 1) & 3));
        long gQ = (long)tile_start * 4 + Q;
        if (gQ > (long)N_EDGES * 4 - 1) gQ = (long)N_EDGES * 4 - 1;  // clamp OOB
        uint32_t dst = sbuf + chunk * 16;
        const char* src = ea + gQ * 16;
        asm volatile("cp.async.cg.shared.global [%0], [%1], 16;" :: "r"(dst), "l"(src));
    }
    asm volatile("cp.async.commit_group;");
}

// Warp-cooperative collapsed weight for one row r of W1.
__device__ __forceinline__ float collapse_row(const float* __restrict__ W1,
                                              const float* __restrict__ w2reg,
                                              int r, int lane) {
    const float* row = W1 + r * HIDDEN;
    float s = 0.f;
    #pragma unroll
    for (int k = 0; k < 5; k++)
        s = fmaf(__ldg(row + lane + 32 * k), w2reg[k], s);
    #pragma unroll
    for (int o = 16; o > 0; o >>= 1)
        s += __shfl_xor_sync(0xFFFFFFFFu, s, o);
    return s;
}

// ---------------------------------------------------------------------------
// Fused persistent kernel (4 blocks/SM), ea streamed via cp.async (2-deep):
//   Stage 0: per-block weight collapse.
//   Prefetch: 2 ea tiles issued async (overlap stages 0-1).
//   Stage 1: node projections p[n] = x[n].w[0:64] (LDG streaming).
//   Stage 2: per tile k: wait+sync, read own row from swizzled smem
//            (conflict-free LDS.128), q[k] = ea.w[64:80]+c, refill tile k+2.
//   Barrier: sense-reversing grid barrier (all blocks resident).
//   Stage 3: 14 scattered p-gathers (p L2-resident), out = sigmoid(ps+q).
// ---------------------------------------------------------------------------
__global__ __launch_bounds__(NTHREADS, 4)
void fused_kernel(const float* __restrict__ x,
                  const void*  __restrict__ ei_raw,
                  const float* __restrict__ ea,
                  const float* __restrict__ W1,
                  const float* __restrict__ b1,
                  const float* __restrict__ W2,
                  const float* __restrict__ b2,
                  float* __restrict__ out) {
    extern __shared__ float4 sbuf_f4[];
    uint32_t sbuf = (uint32_t)__cvta_generic_to_shared(sbuf_f4);

    __shared__ float sw[NUM_PAR];
    __shared__ float sc;
    __shared__ int   smult;
    int t = threadIdx.x;
    int warp = t >> 5;
    int lane = t & 31;

    const int block_edge0 = blockIdx.x * (NTHREADS * EPT);

    // ---- Prefetch first 2 ea tiles (async; overlaps stages 0-1) ----
    #pragma unroll
    for (int k = 0; k < NBUF; k++)
        issue_tile(sbuf + k * TILE_B, (const char*)ea, block_edge0 + k * TILE_E, t);

    // ---- Stage 0: weight collapse (all 8 warps; 10 rows each) ----
    {
        float w2[5];
        #pragma unroll
        for (int k = 0; k < 5; k++) w2[k] = __ldg(W2 + lane + 32 * k);
        #pragma unroll
        for (int rr = 0; rr < 10; rr++) {
            int r = warp * 10 + rr;
            float s = collapse_row(W1, w2, r, lane);
            if (lane == 0) sw[r] = s;
        }
        if (warp == 7) {   // c = b1 . W2 + b2
            float s = 0.f;
            #pragma unroll
            for (int k = 0; k < 5; k++)
                s = fmaf(__ldg(b1 + lane + 32 * k), w2[k], s);
            #pragma unroll
            for (int o = 16; o > 0; o >>= 1)
                s += __shfl_xor_sync(0xFFFFFFFFu, s, o);
            if (lane == 0) sc = s + __ldg(b2);
        }
        if (warp == 0) {
            // Dtype probe: 32 entries as int64 all in [0,N_NODES) <=> int64
            // (int32 data would need 32 zero hi-words: P ~ 1e-160).
            const long long* ei64 = (const long long*)ei_raw;
            long long v = __ldg(ei64 + lane);
            unsigned b = __ballot_sync(0xFFFFFFFFu, v >= 0 && v < N_NODES);
            if (lane == 0) smult = (b == 0xFFFFFFFFu) ? 2 : 1;
        }
    }
    __syncthreads();

    // ---- Stage 1: node projections (2 nodes/warp/iter) ----
    {
        int half = lane >> 4;
        int q    = lane & 15;
        float w0 = sw[q * 4 + 0];
        float w1 = sw[q * 4 + 1];
        float w2r = sw[q * 4 + 2];
        float w3 = sw[q * 4 + 3];

        const float4* x4 = (const float4*)x;
        const int stride = NBLOCKS * 16;

        for (int node = blockIdx.x * 16 + warp * 2 + half;
             node < N_NODES; node += stride) {
            float4 v = __ldg(x4 + (size_t)node * 16 + q);
            float s = fmaf(v.x, w0, fmaf(v.y, w1, fmaf(v.z, w2r, v.w * w3)));
            #pragma unroll
            for (int o = 8; o > 0; o >>= 1)
                s += __shfl_xor_sync(0xFFFFFFFFu, s, o);
            if (q == 0) g_p[node] = s;
        }
    }

    // ---- Index loads (coalesced low-word reads; int32/int64 via mult) ----
    const int mult = smult;
    const float cc = sc;
    const int* eidx = (const int*)ei_raw;
    const int base = block_edge0 + t;

    int srcs[EPT], dsts[EPT];
    #pragma unroll
    for (int k = 0; k < EPT; k++) {
        int e  = base + k * NTHREADS;
        int ec = e < N_EDGES ? e : (N_EDGES - 1);
        srcs[k] = __ldg(eidx + (size_t)mult * ec);
        dsts[k] = __ldg(eidx + (size_t)mult * ((size_t)N_EDGES + ec));
    }

    // ---- Stage 2: consume tiles from smem, refill pipeline ----
    const int swr = (t >> 1) & 3;      // per-thread read swizzle
    float q[EPT];
    #pragma unroll
    for (int k = 0; k < EPT; k++) {
        // Outstanding groups when consuming tile k: min(EPT,k+2)-k.
        if (k < EPT - 1) { CP_WAIT(1); }
        else             { CP_WAIT(0); }
        __syncthreads();             // cross-thread visibility of the tile

        int bq = (k % NBUF) * (TILE_B >> 4);   // buffer base in quads
        float4 a0 = sbuf_f4[bq + t * 4 + (0 ^ swr)];
        float4 a1 = sbuf_f4[bq + t * 4 + (1 ^ swr)];
        float4 a2 = sbuf_f4[bq + t * 4 + (2 ^ swr)];
        float4 a3 = sbuf_f4[bq + t * 4 + (3 ^ swr)];

        float z0 = fmaf(a0.x, sw[64], fmaf(a0.y, sw[65], fmaf(a0.z, sw[66], a0.w * sw[67])));
        float z1 = fmaf(a1.x, sw[68], fmaf(a1.y, sw[69], fmaf(a1.z, sw[70], a1.w * sw[71])));
        float z2 = fmaf(a2.x, sw[72], fmaf(a2.y, sw[73], fmaf(a2.z, sw[74], a2.w * sw[75])));
        float z3 = fmaf(a3.x, sw[76], fmaf(a3.y, sw[77], fmaf(a3.z, sw[78], a3.w * sw[79])));
        q[k] = cc + ((z0 + z1) + (z2 + z3));

        __syncthreads();             // tile fully consumed before refill
        if (k + NBUF < EPT)
            issue_tile(sbuf + ((k + NBUF) % NBUF) * TILE_B, (const char*)ea,
                       block_edge0 + (k + NBUF) * TILE_E, t);
    }

    // ---- Grid barrier (sense-reversing; all blocks resident) ----
    __syncthreads();
    if (t == 0) {
        int gen = g_flag;
        __threadfence();
        int a = atomicAdd(&g_cnt, 1);
        if (a == NBLOCKS - 1) {
            g_cnt = 0;                       // self-reset for next replay
            __threadfence();
            g_flag = gen + 1;                // release
        } else {
            while (g_flag == gen) { }        // spin (volatile)
        }
        __threadfence();
    }
    __syncthreads();

    // ---- Stage 3: scattered gathers + finish ----
    float ps[EPT];
    #pragma unroll
    for (int k = 0; k < EPT; k++)
        ps[k] = g_p[srcs[k]] + g_p[dsts[k]];

    #pragma unroll
    for (int k = 0; k < EPT; k++) {
        int e = base + k * NTHREADS;
        if (e < N_EDGES) {
            float z = ps[k] + q[k];
            out[e] = 1.0f / (1.0f + __expf(-z));
        }
    }
}

extern "C" void kernel_launch(void* const* d_in, const int* in_sizes, int n_in,
                              void* d_out, int out_size) {
    // metadata order: x, edge_index, edge_attr, W1, b1, W2, b2
    const float* x  = (const float*)d_in[0];
    const void*  ei = d_in[1];
    const float* ea = (const float*)d_in[2];
    const float* W1 = (const float*)d_in[3];
    const float* b1 = (const float*)d_in[4];
    const float* W2 = (const float*)d_in[5];
    const float* b2 = (const float*)d_in[6];
    float* out = (float*)d_out;

    fused_kernel<<<NBLOCKS, NTHREADS, SMEM_DYN>>>(x, ei, ea, W1, b1, W2, b2, out);
}

// round 15
// speedup vs baseline: 3.2048x; 3.2048x over previous
#include <cuda_runtime.h>
#include <math.h>

#define N_NODES 100000
#define N_EDGES 1000000
#define D_NODE 64
#define D_EDGE 16
#define NUM_PAR 80
#define HIDDEN 160

#define NBLOCKS 592               // 148 SMs x 4 blocks, all co-resident
#define NTHREADS 256              // 8 warps
#define EPT 7                     // edges per thread: 592*256*7 = 1,060,864 >= 1e6

// Scratch (allocation-free rule).
__device__ float g_p[N_NODES];
__device__ int   g_cnt;           // barrier arrivals (self-resetting)
__device__ volatile int g_flag;   // barrier generation (monotone across replays)

// Warp-cooperative collapsed weight for one row r of W1:
//   w[r] = sum_j W1[r,j] * W2[j], lane-parallel over j (5 strides of 32).
__device__ __forceinline__ float collapse_row(const float* __restrict__ W1,
                                              const float* __restrict__ w2reg,
                                              int r, int lane) {
    const float* row = W1 + r * HIDDEN;
    float s = 0.f;
    #pragma unroll
    for (int k = 0; k < 5; k++)
        s = fmaf(__ldg(row + lane + 32 * k), w2reg[k], s);
    #pragma unroll
    for (int o = 16; o > 0; o >>= 1)
        s += __shfl_xor_sync(0xFFFFFFFFu, s, o);
    return s;   // valid in all lanes
}

// ---------------------------------------------------------------------------
// Fused persistent kernel (4 blocks/SM). R10 structure; seams tightened:
//   Stage 0: per-block weight collapse (W1/W2 L2-resident after wave 1).
//   Index loads hoisted BEFORE stage 1 (latency hides under node stream).
//   Stage 1: node projections p[n] = x[n].w[0:64] (__ldcs, unroll 2).
//   Stage 2 (pre-barrier): q[k] = ea[e].w[64:80] + c, one-edge-ahead
//            pipeline, __ldcs evict-first (one-touch stream).
//   Barrier: sense-reversing grid barrier (all blocks resident by design).
//   Stage 3: 14 scattered p-gathers (L2-resident 400KB), out = sigmoid(ps+q).
// ---------------------------------------------------------------------------
__global__ __launch_bounds__(NTHREADS, 4)
void fused_kernel(const float* __restrict__ x,
                  const void*  __restrict__ ei_raw,
                  const float* __restrict__ ea,
                  const float* __restrict__ W1,
                  const float* __restrict__ b1,
                  const float* __restrict__ W2,
                  const float* __restrict__ b2,
                  float* __restrict__ out) {
    __shared__ float sw[NUM_PAR];
    __shared__ float sc;
    __shared__ int   smult;
    int t = threadIdx.x;
    int warp = t >> 5;
    int lane = t & 31;

    // ---- Stage 0: weight collapse (all 8 warps; 10 rows each) ----
    {
        float w2[5];
        #pragma unroll
        for (int k = 0; k < 5; k++) w2[k] = __ldg(W2 + lane + 32 * k);
        #pragma unroll
        for (int rr = 0; rr < 10; rr++) {
            int r = warp * 10 + rr;
            float s = collapse_row(W1, w2, r, lane);
            if (lane == 0) sw[r] = s;
        }
        if (warp == 7) {   // c = b1 . W2 + b2
            float s = 0.f;
            #pragma unroll
            for (int k = 0; k < 5; k++)
                s = fmaf(__ldg(b1 + lane + 32 * k), w2[k], s);
            #pragma unroll
            for (int o = 16; o > 0; o >>= 1)
                s += __shfl_xor_sync(0xFFFFFFFFu, s, o);
            if (lane == 0) sc = s + __ldg(b2);
        }
        if (warp == 0) {
            // Dtype probe: 32 entries as int64 all in [0,N_NODES) <=> int64
            // (int32 data would need 32 zero hi-words: P ~ 1e-160).
            const long long* ei64 = (const long long*)ei_raw;
            long long v = __ldg(ei64 + lane);
            unsigned b = __ballot_sync(0xFFFFFFFFu, v >= 0 && v < N_NODES);
            if (lane == 0) smult = (b == 0xFFFFFFFFu) ? 2 : 1;
        }
    }
    __syncthreads();

    // ---- Index loads (hoisted: latency overlaps the node stream) ----
    const int mult = smult;
    const int* eidx = (const int*)ei_raw;   // low 4B hold the value (LE)
    const int base = blockIdx.x * (NTHREADS * EPT) + t;

    int srcs[EPT], dsts[EPT];
    #pragma unroll
    for (int k = 0; k < EPT; k++) {
        int e  = base + k * NTHREADS;
        int ec = e < N_EDGES ? e : (N_EDGES - 1);
        srcs[k] = __ldg(eidx + (size_t)mult * ec);
        dsts[k] = __ldg(eidx + (size_t)mult * ((size_t)N_EDGES + ec));
    }

    // ---- Stage 1: node projections (2 nodes/warp/iter, evict-first) ----
    {
        int half = lane >> 4;
        int q    = lane & 15;
        float w0 = sw[q * 4 + 0];
        float w1 = sw[q * 4 + 1];
        float w2r = sw[q * 4 + 2];
        float w3 = sw[q * 4 + 3];

        const float4* x4 = (const float4*)x;
        const int stride = NBLOCKS * 16;

        #pragma unroll 2
        for (int node = blockIdx.x * 16 + warp * 2 + half;
             node < N_NODES; node += stride) {
            float4 v = __ldcs(x4 + (size_t)node * 16 + q);
            float s = fmaf(v.x, w0, fmaf(v.y, w1, fmaf(v.z, w2r, v.w * w3)));
            #pragma unroll
            for (int o = 8; o > 0; o >>= 1)
                s += __shfl_xor_sync(0xFFFFFFFFu, s, o);
            if (q == 0) g_p[node] = s;
        }
    }

    // ---- Stage 2 (pre-barrier): q = ea.w + c, pipelined, evict-first ----
    const float cc = sc;
    float q[EPT];
    float4 c0, c1, c2, c3;
    {
        int e = base < N_EDGES ? base : (N_EDGES - 1);
        const float4* A = (const float4*)(ea + (size_t)e * D_EDGE);
        c0 = __ldcs(A + 0); c1 = __ldcs(A + 1); c2 = __ldcs(A + 2); c3 = __ldcs(A + 3);
    }
    #pragma unroll
    for (int k = 0; k < EPT; k++) {
        float4 n0, n1, n2, n3;
        if (k + 1 < EPT) {
            int e  = base + (k + 1) * NTHREADS;
            int ec = e < N_EDGES ? e : (N_EDGES - 1);
            const float4* A = (const float4*)(ea + (size_t)ec * D_EDGE);
            n0 = __ldcs(A + 0); n1 = __ldcs(A + 1); n2 = __ldcs(A + 2); n3 = __ldcs(A + 3);
        }
        float z0 = fmaf(c0.x, sw[64], fmaf(c0.y, sw[65], fmaf(c0.z, sw[66], c0.w * sw[67])));
        float z1 = fmaf(c1.x, sw[68], fmaf(c1.y, sw[69], fmaf(c1.z, sw[70], c1.w * sw[71])));
        float z2 = fmaf(c2.x, sw[72], fmaf(c2.y, sw[73], fmaf(c2.z, sw[74], c2.w * sw[75])));
        float z3 = fmaf(c3.x, sw[76], fmaf(c3.y, sw[77], fmaf(c3.z, sw[78], c3.w * sw[79])));
        q[k] = cc + ((z0 + z1) + (z2 + z3));
        c0 = n0; c1 = n1; c2 = n2; c3 = n3;
    }

    // ---- Grid barrier (sense-reversing; all blocks resident) ----
    __syncthreads();
    if (t == 0) {
        int gen = g_flag;                    // same value in all blocks:
        __threadfence();                     // flag only moves after all arrive
        int a = atomicAdd(&g_cnt, 1);
        if (a == NBLOCKS - 1) {
            g_cnt = 0;                       // self-reset for next replay
            __threadfence();
            g_flag = gen + 1;                // release
        } else {
            while (g_flag == gen) { }        // spin (volatile)
        }
        __threadfence();
    }
    __syncthreads();

    // ---- Stage 3: scattered gathers + finish ----
    float ps[EPT];
    #pragma unroll
    for (int k = 0; k < EPT; k++)
        ps[k] = g_p[srcs[k]] + g_p[dsts[k]];

    #pragma unroll
    for (int k = 0; k < EPT; k++) {
        int e = base + k * NTHREADS;
        if (e < N_EDGES) {
            float z = ps[k] + q[k];
            out[e] = 1.0f / (1.0f + __expf(-z));
        }
    }
}

extern "C" void kernel_launch(void* const* d_in, const int* in_sizes, int n_in,
                              void* d_out, int out_size) {
    // metadata order: x, edge_index, edge_attr, W1, b1, W2, b2
    const float* x  = (const float*)d_in[0];
    const void*  ei = d_in[1];
    const float* ea = (const float*)d_in[2];
    const float* W1 = (const float*)d_in[3];
    const float* b1 = (const float*)d_in[4];
    const float* W2 = (const float*)d_in[5];
    const float* b2 = (const float*)d_in[6];
    float* out = (float*)d_out;

    fused_kernel<<<NBLOCKS, NTHREADS>>>(x, ei, ea, W1, b1, W2, b2, out);
}